// round 6
// baseline (speedup 1.0000x reference)
#include <cuda_runtime.h>
#include <cuda_bf16.h>
#include <math.h>
#include <stdint.h>

#define TRAJ 1000
#define Bn 512
#define Nn 256
#define Fn 1024   // 4*N
#define Hn 2048
#define On 512

// ================= scratch (static __device__: allocation-free) =================
__device__ float g_cgt[TRAJ], g_csq[TRAJ], g_cent[TRAJ];
__device__ float g_sv[1024];
__device__ int   g_si[1024];
__device__ __nv_bfloat16 g_fH[Bn * Fn],  g_fL[Bn * Fn];    // feats hi/lo [512,1024]
__device__ __nv_bfloat16 g_w1h[Hn * Fn], g_w1l[Hn * Fn];   // W1^T hi/lo [2048,1024]
__device__ __nv_bfloat16 g_w2h[On * Hn], g_w2l[On * Hn];   // W2^T hi/lo [512,2048]
__device__ __nv_bfloat16 g_hH[Bn * Hn],  g_hL[Bn * Hn];    // h hi/lo [512,2048]
__device__ float g_part[4 * Bn * On];                      // split-K partials (Z=4)

// ================= helpers =================
__device__ __forceinline__ uint32_t smem_to_u32(const void* p) {
    uint32_t a;
    asm("{ .reg .u64 t; cvta.to.shared.u64 t, %1; cvt.u32.u64 %0, t; }" : "=r"(a) : "l"(p));
    return a;
}
__device__ __forceinline__ void cp_async16(uint32_t dst, const void* src) {
    asm volatile("cp.async.cg.shared.global [%0], [%1], 16;" :: "r"(dst), "l"(src));
}
__device__ __forceinline__ void cp_commit() { asm volatile("cp.async.commit_group;"); }
__device__ __forceinline__ void cp_wait2()  { asm volatile("cp.async.wait_group 2;"); }
__device__ __forceinline__ void cp_wait1()  { asm volatile("cp.async.wait_group 1;"); }
__device__ __forceinline__ void cp_wait0()  { asm volatile("cp.async.wait_group 0;"); }

__device__ __forceinline__ void ldm_x4(uint32_t* r, uint32_t addr) {
    asm volatile("ldmatrix.sync.aligned.m8n8.x4.shared.b16 {%0,%1,%2,%3}, [%4];"
                 : "=r"(r[0]), "=r"(r[1]), "=r"(r[2]), "=r"(r[3]) : "r"(addr));
}
__device__ __forceinline__ void ldm_x2(uint32_t* r, uint32_t addr) {
    asm volatile("ldmatrix.sync.aligned.m8n8.x2.shared.b16 {%0,%1}, [%2];"
                 : "=r"(r[0]), "=r"(r[1]) : "r"(addr));
}
__device__ __forceinline__ void mma_bf16(float* c, const uint32_t* a, const uint32_t* b) {
    asm volatile("mma.sync.aligned.m16n8k16.row.col.f32.bf16.bf16.f32 "
                 "{%0,%1,%2,%3}, {%4,%5,%6,%7}, {%8,%9}, {%0,%1,%2,%3};"
                 : "+f"(c[0]), "+f"(c[1]), "+f"(c[2]), "+f"(c[3])
                 : "r"(a[0]), "r"(a[1]), "r"(a[2]), "r"(a[3]), "r"(b[0]), "r"(b[1]));
}
__device__ __forceinline__ void bf16_split(float v, __nv_bfloat16& h, __nv_bfloat16& l) {
    h = __float2bfloat16(v);
    l = __float2bfloat16(v - __bfloat162float(h));
}

// ============================================================
// Kernel 1: FUSED prep.
//   block 0          : serial tent map (Markstein exact division) +
//                      two-level prefix scan + bitonic rank-sort
//   blocks 1..2048   : W1 transpose + bf16 hi/lo split
//   blocks 2049..3072: W2 transpose + bf16 hi/lo split
// ============================================================
__global__ void __launch_bounds__(256)
prep_kernel(const float* __restrict__ icp, const float* __restrict__ thp,
            const float* __restrict__ W1, const float* __restrict__ W2) {
    __shared__ float tile[32][33];
    __shared__ float s_traj[TRAJ];
    __shared__ unsigned long long keys[1024];
    __shared__ float red1[256], red2[256], red3[256];

    int t = threadIdx.x;
    int bid = blockIdx.x;

    if (bid != 0) {
        // ---- weight conversion branch ----
        const float* W; __nv_bfloat16 *Th, *Tl;
        int K, N, bx, by;
        if (bid <= 2048) {
            int ti = bid - 1;            // W1: [Fn, Hn] -> T [Hn, Fn]
            W = W1; Th = g_w1h; Tl = g_w1l; K = Fn; N = Hn;
            bx = ti & 63; by = ti >> 6;  // 64 x 32 tiles
        } else {
            int ti = bid - 2049;         // W2: [Hn, On] -> T [On, Hn]
            W = W2; Th = g_w2h; Tl = g_w2l; K = Hn; N = On;
            bx = ti & 15; by = ti >> 4;  // 16 x 64 tiles
        }
        int tx = t & 31, ty = t >> 5;
        int n0 = bx * 32, k0 = by * 32;
        for (int j = ty; j < 32; j += 8)
            tile[j][tx] = W[(size_t)(k0 + j) * N + n0 + tx];
        __syncthreads();
        for (int j = ty; j < 32; j += 8) {
            float v = tile[tx][j];
            size_t o = (size_t)(n0 + j) * K + k0 + tx;
            __nv_bfloat16 h, l; bf16_split(v, h, l);
            Th[o] = h; Tl[o] = l;
        }
        return;
    }

    // ---- special block ----
    if (t == 0) {
        float thv = *thp, c = *icp;
        float omt  = __fadd_rn(1.0f, -thv);
        float rth  = __frcp_rn(thv);    // correctly-rounded reciprocals
        float romt = __frcp_rn(omt);
        s_traj[0] = c;
        for (int i = 1; i < TRAJ; i++) {
            // Markstein: q == RN(a/b) exactly, ~12 cyc vs ~45 for __fdiv_rn
            float q0 = __fmul_rn(c, rth);
            float e  = __fmaf_rn(-thv, q0, c);
            float qa = __fmaf_rn(e, rth, q0);
            float nn = __fadd_rn(1.0f, -c);
            float p0 = __fmul_rn(nn, romt);
            float f  = __fmaf_rn(-omt, p0, nn);
            float qb = __fmaf_rn(f, romt, p0);
            c = (c < thv) ? qa : qb;
            s_traj[i] = c;
        }
    }
    __syncthreads();

    // two-level exclusive prefix scan of the 3 term sequences (250 x 4 elems)
    float b1v[4], b2v[4], b3v[4];
    if (t < 250) {
        float a1 = 0.f, a2 = 0.f, a3 = 0.f;
#pragma unroll
        for (int q = 0; q < 4; q++) {
            float v = s_traj[t * 4 + q];
            b1v[q] = a1; b2v[q] = a2; b3v[q] = a3;
            a1 += (v > 0.5f) ? 1.0f : 0.0f;
            a2 += v * v;
            a3 += v * log2f(v + 1e-10f);
        }
        red1[t] = a1; red2[t] = a2; red3[t] = a3;
    }
    __syncthreads();
    if (t == 0) {
        float r1 = 0.f, r2 = 0.f, r3 = 0.f;
        for (int i = 0; i < 250; i++) {
            float x1 = red1[i], x2 = red2[i], x3 = red3[i];
            red1[i] = r1; red2[i] = r2; red3[i] = r3;
            r1 += x1; r2 += x2; r3 += x3;
        }
    }
    __syncthreads();
    if (t < 250) {
#pragma unroll
        for (int q = 0; q < 4; q++) {
            g_cgt[t * 4 + q]  = red1[t] + b1v[q];
            g_csq[t * 4 + q]  = red2[t] + b2v[q];
            g_cent[t * 4 + q] = red3[t] + b3v[q];
        }
    }

    // bitonic sort on packed (floatbits<<32 | idx) keys: stable rank order
    for (int j = t; j < 1024; j += 256) {
        unsigned long long key;
        if (j < TRAJ)
            key = ((unsigned long long)__float_as_uint(s_traj[j]) << 32) | (unsigned)j;
        else
            key = ((unsigned long long)0x7F800000u << 32) | (unsigned)j;  // +inf pad
        keys[j] = key;
    }
    __syncthreads();
    for (int k = 2; k <= 1024; k <<= 1) {
        for (int j2 = k >> 1; j2 > 0; j2 >>= 1) {
            for (int p = t; p < 1024; p += 256) {
                int l = p ^ j2;
                if (l > p) {
                    bool asc = ((p & k) == 0);
                    unsigned long long a = keys[p], b = keys[l];
                    if (asc ? (a > b) : (a < b)) { keys[p] = b; keys[l] = a; }
                }
            }
            __syncthreads();
        }
    }
    for (int j = t; j < 1024; j += 256) {
        g_sv[j] = __uint_as_float((uint32_t)(keys[j] >> 32));
        g_si[j] = (int)(uint32_t)keys[j];
    }
}

// ============================================================
// Kernel 2: features (binary-search argmin), writes bf16 hi/lo
// ============================================================
__global__ void features_kernel(const float* __restrict__ X) {
    __shared__ float s_sv[1024];
    __shared__ int   s_si[TRAJ];
    __shared__ float s_cgt[TRAJ], s_csq[TRAJ], s_cent[TRAJ];
    int tid = threadIdx.x;
    for (int j = tid; j < 1024; j += 256) s_sv[j] = g_sv[j];
    for (int j = tid; j < TRAJ; j += 256) {
        s_si[j] = g_si[j]; s_cgt[j] = g_cgt[j]; s_csq[j] = g_csq[j]; s_cent[j] = g_cent[j];
    }
    __syncthreads();

    float x = X[blockIdx.x * Nn + tid];
    int lo = 0;
#pragma unroll
    for (int step = 512; step > 0; step >>= 1)
        if (s_sv[lo + step - 1] < x) lo += step;

    const float INF = __int_as_float(0x7f800000);
    float dl = (lo > 0)    ? fabsf(x - s_sv[lo - 1]) : INF;
    float dr = (lo < TRAJ) ? fabsf(x - s_sv[lo])     : INF;
    float d = fminf(dl, dr);
    int mi = 0x7fffffff;
    if (dl == d)
        for (int k = lo - 1; k >= 0 && fabsf(x - s_sv[k]) == d; --k) mi = min(mi, s_si[k]);
    if (dr == d)
        for (int k = lo; k < TRAJ && fabsf(x - s_sv[k]) == d; ++k) mi = min(mi, s_si[k]);

    int idx = mi;
    float tt = (float)idx;
    float f[4];
    f[0] = (idx > 0) ? __fdiv_rn(s_cgt[idx], tt) : 0.0f;
    f[1] = s_csq[idx];
    f[2] = tt;
    f[3] = -s_cent[idx];
    size_t o = (size_t)blockIdx.x * Fn + tid * 4;
#pragma unroll
    for (int j = 0; j < 4; j++) bf16_split(f[j], g_fH[o + j], g_fL[o + j]);
}

// ============================================================
// Kernel 3: warp-MMA bf16 3-pass GEMM. CTA tile 64(M)x64(N), BK=32,
// 128 threads, 4 warps (2x2), warp tile 32x32, 3-stage cp.async pipeline.
//   EPI=1: epilogue fuses bias + ReLU + bf16 hi/lo split -> outH/outL
//   EPI=0: writes fp32 split-K partials -> part[z]
// ============================================================
#define TS 40                          // smem row stride (bf16) = 80 B, conflict-free
#define ARR_B (64 * TS * 2)            // 5120 B per array tile (64 rows)
#define STG_B (4 * ARR_B)              // 20480 B per stage (Ah,Al,Bh,Bl)
#define O_AH 0
#define O_AL ARR_B
#define O_BH (2 * ARR_B)
#define O_BL (3 * ARR_B)

template <int EPI>
__global__ void __launch_bounds__(128)
gemm_mma(const __nv_bfloat16* __restrict__ Ah, const __nv_bfloat16* __restrict__ Al,
         const __nv_bfloat16* __restrict__ Bh, const __nv_bfloat16* __restrict__ Bl,
         const float* __restrict__ bias, __nv_bfloat16* __restrict__ outH,
         __nv_bfloat16* __restrict__ outL, float* __restrict__ part,
         int K, int Ntot, int M) {
    extern __shared__ char sm[];
    uint32_t sb = smem_to_u32(sm);
    int tid = threadIdx.x, wid = tid >> 5, lid = tid & 31;
    int wm = wid >> 1, wn = wid & 1;            // 2 x 2 warp grid, warp tile 32x32

    int m0 = blockIdx.y * 64, n0 = blockIdx.x * 64, z = blockIdx.z;
    int kLen = K / gridDim.z, k0 = z * kLen;
    int nChunks = kLen / 32;

    // prefetch mapping: r = tid>>2 (0..31), seg = tid&3 (16B within 64B row); +32-row iter
    int pr = tid >> 2, ps = tid & 3;
    uint32_t sO = (uint32_t)(pr * 80 + ps * 16);
    size_t gA0 = ((size_t)(m0 + pr) * K + k0) * 2 + ps * 16;
    size_t gB0 = ((size_t)(n0 + pr) * K + k0) * 2 + ps * 16;
    size_t rowAdv = (size_t)32 * K * 2;

#define PREFETCH(c, b) do {                                                        \
    size_t kb = (size_t)(c) * 64;                                                  \
    uint32_t base = sb + (uint32_t)(b) * STG_B;                                    \
    cp_async16(base + O_AH + sO,             (const char*)Ah + gA0 + kb);          \
    cp_async16(base + O_AH + sO + 32 * 80,   (const char*)Ah + gA0 + kb + rowAdv); \
    cp_async16(base + O_AL + sO,             (const char*)Al + gA0 + kb);          \
    cp_async16(base + O_AL + sO + 32 * 80,   (const char*)Al + gA0 + kb + rowAdv); \
    cp_async16(base + O_BH + sO,             (const char*)Bh + gB0 + kb);          \
    cp_async16(base + O_BH + sO + 32 * 80,   (const char*)Bh + gB0 + kb + rowAdv); \
    cp_async16(base + O_BL + sO,             (const char*)Bl + gB0 + kb);          \
    cp_async16(base + O_BL + sO + 32 * 80,   (const char*)Bl + gB0 + kb + rowAdv); \
    cp_commit();                                                                   \
} while (0)

    float acc[2][4][4];
#pragma unroll
    for (int i = 0; i < 2; i++)
#pragma unroll
        for (int j = 0; j < 4; j++)
#pragma unroll
            for (int k = 0; k < 4; k++) acc[i][j][k] = 0.f;

    int lr = lid & 7, sub = lid >> 3;
    int aRow = wm * 32 + ((sub & 1) << 3) + lr;   // + mt*16
    int aK   = (sub >> 1) << 3;
    int bRow = wn * 32 + lr;                      // + nt*8
    int bK   = (sub & 1) << 3;

    PREFETCH(0, 0);
    if (nChunks > 1) PREFETCH(1, 1);

    for (int c = 0; c < nChunks; c++) {
        if (c + 2 < nChunks) { PREFETCH(c + 2, (c + 2) % 3); cp_wait2(); }
        else if (c + 1 < nChunks) cp_wait1();
        else cp_wait0();
        __syncthreads();

        uint32_t base = sb + (uint32_t)(c % 3) * STG_B;

        // preload ALL fragments for both k-steps, then burst the 48 MMAs
        uint32_t ah[2][2][4], al[2][2][4], bh[2][4][2], bl[2][4][2];
#pragma unroll
        for (int ks = 0; ks < 2; ks++) {
            int kb = ks * 16;
#pragma unroll
            for (int mt = 0; mt < 2; mt++) {
                uint32_t ao = base + (uint32_t)((aRow + mt * 16) * TS + kb + aK) * 2;
                ldm_x4(ah[ks][mt], ao + O_AH);
                ldm_x4(al[ks][mt], ao + O_AL);
            }
#pragma unroll
            for (int nt = 0; nt < 4; nt++) {
                uint32_t bo = base + (uint32_t)((bRow + nt * 8) * TS + kb + bK) * 2;
                ldm_x2(bh[ks][nt], bo + O_BH);
                ldm_x2(bl[ks][nt], bo + O_BL);
            }
        }
#pragma unroll
        for (int ks = 0; ks < 2; ks++)
#pragma unroll
            for (int mt = 0; mt < 2; mt++)
#pragma unroll
                for (int nt = 0; nt < 4; nt++) {
                    mma_bf16(acc[mt][nt], ah[ks][mt], bh[ks][nt]);
                    mma_bf16(acc[mt][nt], ah[ks][mt], bl[ks][nt]);
                    mma_bf16(acc[mt][nt], al[ks][mt], bh[ks][nt]);
                }
        __syncthreads();
    }

    int rg = lid >> 2, cg = (lid & 3) * 2;
#pragma unroll
    for (int mt = 0; mt < 2; mt++) {
        int row = m0 + wm * 32 + mt * 16 + rg;
#pragma unroll
        for (int nt = 0; nt < 4; nt++) {
            int col = n0 + wn * 32 + nt * 8 + cg;
            if (EPI == 1) {
                float2 bi = *(const float2*)&bias[col];
#pragma unroll
                for (int hrow = 0; hrow < 2; hrow++) {
                    int r = row + hrow * 8;
                    float v0 = fmaxf(acc[mt][nt][hrow * 2 + 0] + bi.x, 0.f);
                    float v1 = fmaxf(acc[mt][nt][hrow * 2 + 1] + bi.y, 0.f);
                    __nv_bfloat16 h0, l0, h1, l1;
                    bf16_split(v0, h0, l0); bf16_split(v1, h1, l1);
                    *(__nv_bfloat162*)&outH[(size_t)r * Ntot + col] = __nv_bfloat162(h0, h1);
                    *(__nv_bfloat162*)&outL[(size_t)r * Ntot + col] = __nv_bfloat162(l0, l1);
                }
            } else {
                float* dst = part + (size_t)z * M * Ntot;
                *(float2*)&dst[(size_t)row * Ntot + col] =
                    make_float2(acc[mt][nt][0], acc[mt][nt][1]);
                *(float2*)&dst[(size_t)(row + 8) * Ntot + col] =
                    make_float2(acc[mt][nt][2], acc[mt][nt][3]);
            }
        }
    }
}

// ============================================================
// Kernel 4: combine GEMM2 split-K (Z=4) + bias b2 -> out
// ============================================================
__global__ void combine2(const float* __restrict__ b2, float* __restrict__ out) {
    int i = blockIdx.x * 256 + threadIdx.x;
    float s = b2[i & (On - 1)];
#pragma unroll
    for (int zz = 0; zz < 4; zz++) s += g_part[zz * Bn * On + i];
    out[i] = s;
}

// ============================================================
extern "C" void kernel_launch(void* const* d_in, const int* in_sizes, int n_in,
                              void* d_out, int out_size) {
    const float* x  = (const float*)d_in[0];
    const float* W1 = (const float*)d_in[1];
    const float* b1 = (const float*)d_in[2];
    const float* W2 = (const float*)d_in[3];
    const float* b2 = (const float*)d_in[4];
    const float* ic = (const float*)d_in[5];
    const float* th = (const float*)d_in[6];
    float* out = (float*)d_out;

    __nv_bfloat16 *fH, *fL, *w1h, *w1l, *w2h, *w2l, *hH, *hL;
    float* part;
    cudaGetSymbolAddress((void**)&fH,  g_fH);  cudaGetSymbolAddress((void**)&fL,  g_fL);
    cudaGetSymbolAddress((void**)&w1h, g_w1h); cudaGetSymbolAddress((void**)&w1l, g_w1l);
    cudaGetSymbolAddress((void**)&w2h, g_w2h); cudaGetSymbolAddress((void**)&w2l, g_w2l);
    cudaGetSymbolAddress((void**)&hH,  g_hH);  cudaGetSymbolAddress((void**)&hL,  g_hL);
    cudaGetSymbolAddress((void**)&part, g_part);

    const int SMEM_SZ = 3 * STG_B;  // 61440
    cudaFuncSetAttribute(gemm_mma<1>, cudaFuncAttributeMaxDynamicSharedMemorySize, SMEM_SZ);
    cudaFuncSetAttribute(gemm_mma<0>, cudaFuncAttributeMaxDynamicSharedMemorySize, SMEM_SZ);

    // fused: serial trajectory/scan/sort (block 0) || W1/W2 convert (3072 blocks)
    prep_kernel<<<3073, 256>>>(ic, th, W1, W2);
    features_kernel<<<Bn, Nn>>>(x);
    // GEMM1: [512,1024]x[1024,2048], Z=1, fused bias+relu+split -> h  (256 CTAs)
    gemm_mma<1><<<dim3(Hn / 64, Bn / 64, 1), 128, SMEM_SZ>>>(
        fH, fL, w1h, w1l, b1, hH, hL, nullptr, Fn, Hn, Bn);
    // GEMM2: [512,2048]x[2048,512], Z=4 -> partials  (256 CTAs)
    gemm_mma<0><<<dim3(On / 64, Bn / 64, 4), 128, SMEM_SZ>>>(
        hH, hL, w2h, w2l, nullptr, nullptr, nullptr, part, Hn, On, Bn);
    combine2<<<(Bn * On) / 256, 256>>>(b2, out);
}